// round 12
// baseline (speedup 1.0000x reference)
#include <cuda_runtime.h>
#include <cstddef>
#include <cstdint>

// Problem constants
#define N_SEQ   64
#define L_SEQ   512
#define D_IN    1280
#define M_ROWS  (N_SEQ * L_SEQ)     // 32768 (n,l) rows
#define COLS    36                   // 32 proj outputs + 1 token col + 3 pad
#define N_TILES 8                    // 512 / 64
#define N_PAIRS 36                   // upper-tri tile pairs (lb <= mb)
#define SCALE_CONST 0.08838834764831845f  // 1/(4*sqrt(8))

// Scratch (static device globals: no allocation in kernel_launch)
__device__ float g_h[M_ROWS * 32];          // projected h, [32768][32]
__device__ float g_fo[M_ROWS / 128];        // per-block first-order partials (256)
__device__ float g_partial[N_SEQ * N_PAIRS];// per-tile second-order partials

// ---- packed fp32x2 helpers (sm_100+ only; ptxas will not auto-fuse) ----
__device__ __forceinline__ void fma2(unsigned long long &d,
                                     unsigned long long a,
                                     unsigned long long b) {
    asm("fma.rn.f32x2 %0, %1, %2, %0;" : "+l"(d) : "l"(a), "l"(b));
}
__device__ __forceinline__ float hsum2(unsigned long long u) {
    float lo, hi;
    asm("mov.b64 {%0, %1}, %2;" : "=f"(lo), "=f"(hi) : "l"(u));
    return lo + hi;
}

// ---- cp.async helpers ----
__device__ __forceinline__ void cp_async8(uint32_t dst, const void* src) {
    asm volatile("cp.async.ca.shared.global [%0], [%1], 8;" :: "r"(dst), "l"(src));
}
__device__ __forceinline__ void cp_commit() {
    asm volatile("cp.async.commit_group;" ::: "memory");
}
__device__ __forceinline__ void cp_wait_all() {
    asm volatile("cp.async.wait_group 0;" ::: "memory");
}

// ---------------------------------------------------------------------------
// K1: projection GEMM. C[32768, 36] = x[32768,1280] @ [W_proj; w_token; 0]^T.
// Block: 192 threads (6 warps), tile 128 rows x 36 cols, K-chunks of 32.
// cp.async double-buffered smem (no register staging -> deep LDS pipelining).
// Thread micro-tile: 4 rows (strided by 32) x 6 cols, f32x2 packed along K.
// Epilogue: smem-staged coalesced STG.128 of h + per-block first-order dot.
// ---------------------------------------------------------------------------
#define KC        32
#define KPAD_X    38          // pair stride 19, gcd(19,16)=1 -> conflict-free
#define KPAD_W    34          // broadcast reads; 8B-aligned rows
#define TILE_ROWS 128
#define K1_THREADS 192
#define NE2_X     (TILE_ROWS * KC / 2)          // 2048 float2 of x per chunk
#define NE2_TOT   (NE2_X + 33 * KC / 2)         // + 528 = 2576 total
#define NCP       14                             // ceil(2576/192)

__global__ __launch_bounds__(K1_THREADS, 2)
void proj_kernel(const float* __restrict__ x,
                 const float* __restrict__ W_proj,
                 const float* __restrict__ w_token,
                 const float* __restrict__ w_seq) {
    __shared__ float xs[2][TILE_ROWS][KPAD_X];
    __shared__ float ws[2][COLS][KPAD_W];
    __shared__ float fored[6];

    const int tid  = threadIdx.x;
    const int warp = tid >> 5;      // 0..5 -> column group
    const int lane = tid & 31;      // row within stride group
    const int rowbase = blockIdx.x * TILE_ROWS;

    const uint32_t sm_xs = (uint32_t)__cvta_generic_to_shared(&xs[0][0][0]);
    const uint32_t sm_ws = (uint32_t)__cvta_generic_to_shared(&ws[0][0][0]);

    // zero the 3 pad weight rows (33..35) in both buffers once
    for (int i = tid; i < 2 * 3 * KPAD_W; i += K1_THREADS) {
        int b  = i / (3 * KPAD_W);
        int rr = (i - b * 3 * KPAD_W) / KPAD_W;
        int p  = i - b * 3 * KPAD_W - rr * KPAD_W;
        ws[b][33 + rr][p] = 0.0f;
    }

    unsigned long long acc[4][6];
#pragma unroll
    for (int i = 0; i < 4; i++)
#pragma unroll
        for (int j = 0; j < 6; j++) acc[i][j] = 0ULL;

    auto prefetch = [&](int kb, int b) {
#pragma unroll
        for (int it = 0; it < NCP; it++) {
            int e = tid + it * K1_THREADS;
            if (e < NE2_TOT) {
                if (e < NE2_X) {
                    int r = e >> 4;               // 16 float2 per row
                    int p = (e & 15) << 1;        // float offset
                    cp_async8(sm_xs + (((b * TILE_ROWS + r) * KPAD_X + p) << 2),
                              x + (size_t)(rowbase + r) * D_IN + kb + p);
                } else {
                    int j = e - NE2_X;
                    int r = j >> 4;               // 0..32
                    int p = (j & 15) << 1;
                    const float* src = (r < 32)
                        ? W_proj + (size_t)r * D_IN + kb + p
                        : w_token + kb + p;
                    cp_async8(sm_ws + (((b * COLS + r) * KPAD_W + p) << 2), src);
                }
            }
        }
        cp_commit();
    };

    prefetch(0, 0);

    const int NCHUNK = D_IN / KC;   // 40
    for (int c = 0; c < NCHUNK; c++) {
        const int b = c & 1;
        cp_wait_all();              // chunk c (sole pending group) landed
        __syncthreads();            // publish chunk c; all warps past compute(c-1)

        if (c + 1 < NCHUNK)
            prefetch((c + 1) * KC, b ^ 1);   // flies during compute below

#pragma unroll 4
        for (int k2 = 0; k2 < KC / 2; k2++) {
            unsigned long long xv[4], wv[6];
#pragma unroll
            for (int i = 0; i < 4; i++)
                xv[i] = *(const unsigned long long*)&xs[b][lane + (i << 5)][k2 * 2];
#pragma unroll
            for (int j = 0; j < 6; j++)
                wv[j] = *(const unsigned long long*)&ws[b][warp * 6 + j][k2 * 2];
#pragma unroll
            for (int i = 0; i < 4; i++)
#pragma unroll
                for (int j = 0; j < 6; j++)
                    fma2(acc[i][j], xv[i], wv[j]);
        }
    }
    __syncthreads();   // all compute done before xs[0] is reused for staging

    // epilogue: stage results in xs[0], then coalesced STG.128 writeout.
#pragma unroll
    for (int i = 0; i < 4; i++) {
        int r = lane + (i << 5);
#pragma unroll
        for (int j = 0; j < 6; j++)
            xs[0][r][warp * 6 + j] = hsum2(acc[i][j]);
    }
    __syncthreads();

    for (int i = tid; i < TILE_ROWS * 8; i += K1_THREADS) {
        int r = i >> 3;
        int q = (i & 7) << 2;
        float4 v = make_float4(xs[0][r][q], xs[0][r][q + 1],
                               xs[0][r][q + 2], xs[0][r][q + 3]);
        *(float4*)(g_h + (size_t)(rowbase + r) * 32 + q) = v;
    }

    // first-order partial: rows of this block are l = l0 + r within one n.
    {
        const int l0 = rowbase & (L_SEQ - 1);
        float fo = (tid < TILE_ROWS) ? xs[0][tid][32] * w_seq[l0 + tid] : 0.0f;
#pragma unroll
        for (int off = 16; off; off >>= 1)
            fo += __shfl_down_sync(0xffffffffu, fo, off);
        if (lane == 0) fored[warp] = fo;
        __syncthreads();
        if (tid == 0) {
            float s = 0.0f;
#pragma unroll
            for (int w = 0; w < 6; w++) s += fored[w];
            g_fo[blockIdx.x] = s;
        }
    }
}

// ---------------------------------------------------------------------------
// K2: second-order. For tile pair (lb<=mb) of sequence positions, compute
// G = Hl @ Hm^T (64x64, K=32), multiply by priors with strict upper mask,
// reduce to a deterministic per-block partial.
// ---------------------------------------------------------------------------
#define HPAD 34

__global__ __launch_bounds__(256)
void attn_kernel(const float* __restrict__ priors) {
    __shared__ float hl[64][HPAD];
    __shared__ float hm[64][HPAD];
    __shared__ float red[8];

    const int bx = blockIdx.x;
    const int n  = bx / N_PAIRS;
    const int tp = bx - n * N_PAIRS;

    // decode upper-tri tile pair
    int lb = 0, rem = tp;
#pragma unroll
    for (int q = 0; q < N_TILES; q++) {
        int cnt = N_TILES - q;
        if (rem < cnt) { lb = q; break; }
        rem -= cnt;
    }
    const int mb = lb + rem;

    const int tid = threadIdx.x;
    const float* Hl = g_h + (size_t)(n * L_SEQ + lb * 64) * 32;
    const float* Hm = g_h + (size_t)(n * L_SEQ + mb * 64) * 32;

    // load both 64x32 H tiles (512 float4 each)
    for (int i = tid; i < 512; i += 256) {
        int r  = i >> 3;
        int k4 = (i & 7) << 2;
        float4 v = *(const float4*)(Hl + r * 32 + k4);
        *(float2*)&hl[r][k4]     = make_float2(v.x, v.y);
        *(float2*)&hl[r][k4 + 2] = make_float2(v.z, v.w);
        float4 u = *(const float4*)(Hm + r * 32 + k4);
        *(float2*)&hm[r][k4]     = make_float2(u.x, u.y);
        *(float2*)&hm[r][k4 + 2] = make_float2(u.z, u.w);
    }
    __syncthreads();

    const int lg = tid >> 4;   // 0..15
    const int mg = tid & 15;   // 0..15

    unsigned long long acc[4][4];
#pragma unroll
    for (int i = 0; i < 4; i++)
#pragma unroll
        for (int j = 0; j < 4; j++) acc[i][j] = 0ULL;

#pragma unroll 4
    for (int k2 = 0; k2 < 16; k2++) {
        unsigned long long a[4], b[4];
#pragma unroll
        for (int i = 0; i < 4; i++)
            a[i] = *(const unsigned long long*)&hl[lg + (i << 4)][k2 * 2];
#pragma unroll
        for (int j = 0; j < 4; j++)
            b[j] = *(const unsigned long long*)&hm[mg + (j << 4)][k2 * 2];
#pragma unroll
        for (int i = 0; i < 4; i++)
#pragma unroll
            for (int j = 0; j < 4; j++)
                fma2(acc[i][j], a[i], b[j]);
    }

    // apply priors with strict upper-tri mask, accumulate
    float partial = 0.0f;
    const float* P = priors + (size_t)n * L_SEQ * L_SEQ;
#pragma unroll
    for (int i = 0; i < 4; i++) {
        int l = lb * 64 + lg + (i << 4);
#pragma unroll
        for (int j = 0; j < 4; j++) {
            int m = mb * 64 + mg + (j << 4);
            if (m > l)
                partial += hsum2(acc[i][j]) * __ldg(&P[(size_t)l * L_SEQ + m]);
        }
    }

    // deterministic block reduce
#pragma unroll
    for (int off = 16; off; off >>= 1)
        partial += __shfl_down_sync(0xffffffffu, partial, off);
    if ((tid & 31) == 0) red[tid >> 5] = partial;
    __syncthreads();
    if (tid == 0) {
        float s = 0.0f;
#pragma unroll
        for (int w = 0; w < 8; w++) s += red[w];
        g_partial[bx] = s;
    }
}

// ---------------------------------------------------------------------------
// K3: finalize. out[n] = sum(4 fo partials) + b + scale*IS*sum(36 partials)
// ---------------------------------------------------------------------------
__global__ __launch_bounds__(64)
void final_kernel(const float* __restrict__ b_seq,
                  const float* __restrict__ iscale,
                  float* __restrict__ out) {
    const int n   = blockIdx.x;
    const int tid = threadIdx.x;
    __shared__ float red[2];

    const float sc = SCALE_CONST * iscale[0];
    float s = 0.0f;
    if (tid < 4)       s += g_fo[n * 4 + tid];
    if (tid < N_PAIRS) s += sc * g_partial[n * N_PAIRS + tid];

#pragma unroll
    for (int off = 16; off; off >>= 1)
        s += __shfl_down_sync(0xffffffffu, s, off);
    if ((tid & 31) == 0) red[tid >> 5] = s;
    __syncthreads();
    if (tid == 0) out[n] = red[0] + red[1] + b_seq[0];
}

// ---------------------------------------------------------------------------
extern "C" void kernel_launch(void* const* d_in, const int* in_sizes, int n_in,
                              void* d_out, int out_size) {
    const float* x        = (const float*)d_in[0];  // (64,512,1280)
    const float* priors   = (const float*)d_in[1];  // (64,512,512)
    const float* w_token  = (const float*)d_in[2];  // (1280)
    const float* w_seq    = (const float*)d_in[3];  // (512)
    const float* b_seq    = (const float*)d_in[4];  // scalar
    const float* W_proj   = (const float*)d_in[5];  // (32,1280)
    const float* iscale   = (const float*)d_in[6];  // scalar
    float* out = (float*)d_out;                     // (64)

    proj_kernel<<<M_ROWS / TILE_ROWS, K1_THREADS>>>(x, W_proj, w_token, w_seq);
    attn_kernel<<<N_SEQ * N_PAIRS, 256>>>(priors);
    final_kernel<<<N_SEQ, 64>>>(b_seq, iscale, out);
}